// round 3
// baseline (speedup 1.0000x reference)
#include <cuda_runtime.h>
#include <math.h>

#define N_NODES 50000
#define N_EDGES 800000
#define DIM 128
#define EPS_BETA 1e-6f
#define EPS_BN 1e-5f

// ---------------- scratch (device globals; no allocation allowed) ----------
__device__ float  d_z[N_NODES * DIM];      // fc output
__device__ float  d_ssrc[N_NODES];         // z . w_src
__device__ float  d_sdst[N_NODES];         // z . w_dst
__device__ float  d_e[N_EDGES];            // e -> ex -> (reused)
__device__ float  d_coef[N_EDGES];         // alpha*beta per edge
__device__ float  d_m[N_NODES];            // segment max
__device__ float  d_denom[N_NODES];        // segment sum of ex
__device__ float  d_bsum[N_NODES];         // segment sum of sigma
__device__ float  d_hnew[N_NODES * DIM];   // aggregated output (pre-BN)
__device__ double d_colsum[DIM];
__device__ double d_colsq[DIM];
__device__ float  d_scale[DIM];
__device__ float  d_shift[DIM];

// ---------------- init ------------------------------------------------------
__global__ void init_kernel() {
    int i = blockIdx.x * blockDim.x + threadIdx.x;
    int stride = gridDim.x * blockDim.x;
    for (int idx = i; idx < N_NODES * DIM; idx += stride) d_hnew[idx] = 0.0f;
    for (int idx = i; idx < N_NODES; idx += stride) {
        d_m[idx] = -INFINITY;
        d_denom[idx] = 0.0f;
        d_bsum[idx] = 0.0f;
    }
    if (i < DIM) { d_colsum[i] = 0.0; d_colsq[i] = 0.0; }
}

// ---------------- GEMM: z = h @ fc_w + fc_b, fused attention projections ----
// block: 256 threads = 8 warps. Block computes 64 rows x 128 cols.
// warp ty handles rows [base + ty*8, base + ty*8 + 7]; lane tx handles cols 4tx..4tx+3.
__global__ void gemm_kernel(const float* __restrict__ h,
                            const float* __restrict__ fc_w,
                            const float* __restrict__ fc_b,
                            const float* __restrict__ attn_w) {
    __shared__ float hs[64][DIM];   // 32 KB

    const int base = blockIdx.x * 64;
    const int t  = threadIdx.x;
    const int tx = t & 31;
    const int ty = t >> 5;

    // stage h tile (guard partial last block)
    {
        float4* hs4 = reinterpret_cast<float4*>(&hs[0][0]);
        const float4* hg = reinterpret_cast<const float4*>(h + (size_t)base * DIM);
        const int nvec = 64 * DIM / 4;                 // 2048 float4
        const int valid_rows = min(64, N_NODES - base);
        const int valid_vec = valid_rows * DIM / 4;
        for (int i = t; i < nvec; i += 256) {
            float4 v = (i < valid_vec) ? __ldg(hg + i) : make_float4(0.f, 0.f, 0.f, 0.f);
            hs4[i] = v;
        }
    }
    __syncthreads();

    float4 acc[8];
#pragma unroll
    for (int r = 0; r < 8; r++) acc[r] = make_float4(0.f, 0.f, 0.f, 0.f);

#pragma unroll 4
    for (int k = 0; k < DIM; k++) {
        float4 w4 = __ldg(reinterpret_cast<const float4*>(fc_w + (size_t)k * DIM) + tx);
#pragma unroll
        for (int r = 0; r < 8; r++) {
            float hv = hs[ty * 8 + r][k];
            acc[r].x = fmaf(hv, w4.x, acc[r].x);
            acc[r].y = fmaf(hv, w4.y, acc[r].y);
            acc[r].z = fmaf(hv, w4.z, acc[r].z);
            acc[r].w = fmaf(hv, w4.w, acc[r].w);
        }
    }

    float4 b4   = __ldg(reinterpret_cast<const float4*>(fc_b) + tx);
    float4 wsrc = __ldg(reinterpret_cast<const float4*>(attn_w) + tx);
    float4 wdst = __ldg(reinterpret_cast<const float4*>(attn_w + DIM) + tx);

#pragma unroll
    for (int r = 0; r < 8; r++) {
        int row = base + ty * 8 + r;
        if (row >= N_NODES) break;
        float4 zv;
        zv.x = acc[r].x + b4.x;
        zv.y = acc[r].y + b4.y;
        zv.z = acc[r].z + b4.z;
        zv.w = acc[r].w + b4.w;
        reinterpret_cast<float4*>(d_z + (size_t)row * DIM)[tx] = zv;

        float ps = zv.x * wsrc.x + zv.y * wsrc.y + zv.z * wsrc.z + zv.w * wsrc.w;
        float pd = zv.x * wdst.x + zv.y * wdst.y + zv.z * wdst.z + zv.w * wdst.w;
#pragma unroll
        for (int off = 16; off > 0; off >>= 1) {
            ps += __shfl_down_sync(0xFFFFFFFFu, ps, off);
            pd += __shfl_down_sync(0xFFFFFFFFu, pd, off);
        }
        if (tx == 0) { d_ssrc[row] = ps; d_sdst[row] = pd; }
    }
}

// ---------------- edge pass 1: e + segment max ------------------------------
__device__ __forceinline__ void atomicMaxF(float* addr, float val) {
    int* ai = reinterpret_cast<int*>(addr);
    int old = *reinterpret_cast<volatile int*>(ai);
    while (__int_as_float(old) < val) {
        int assumed = old;
        old = atomicCAS(ai, assumed, __float_as_int(val));
        if (old == assumed) break;
    }
}

__global__ void edge1_kernel(const int* __restrict__ src, const int* __restrict__ dst,
                             const float* __restrict__ attn_b) {
    int i = blockIdx.x * blockDim.x + threadIdx.x;
    if (i >= N_EDGES) return;
    float a = d_ssrc[__ldg(src + i)] + d_sdst[__ldg(dst + i)] + __ldg(attn_b);
    float e = (a > 0.f) ? a : 0.01f * a;
    d_e[i] = e;
    atomicMaxF(&d_m[__ldg(dst + i)], e);
}

// ---------------- edge pass 2: exp + segment sums ---------------------------
__global__ void edge2_kernel(const int* __restrict__ dst,
                             const float* __restrict__ sigma) {
    int i = blockIdx.x * blockDim.x + threadIdx.x;
    if (i >= N_EDGES) return;
    int d = __ldg(dst + i);
    float ex = expf(d_e[i] - d_m[d]);
    d_e[i] = ex;
    atomicAdd(&d_denom[d], ex);
    atomicAdd(&d_bsum[d], __ldg(sigma + i));
}

// ---------------- edge pass 3: per-edge coefficient -------------------------
__global__ void edge3_kernel(const int* __restrict__ dst,
                             const float* __restrict__ sigma) {
    int i = blockIdx.x * blockDim.x + threadIdx.x;
    if (i >= N_EDGES) return;
    int d = __ldg(dst + i);
    float alpha = d_e[i] / d_denom[d];
    float beta  = __ldg(sigma + i) / (d_bsum[d] + EPS_BETA);
    d_coef[i] = alpha * beta;
}

// ---------------- scatter aggregation: h_new[dst] += coef * z[src] ----------
// one warp per edge, lane handles 4 consecutive floats, vector red.add
__global__ void scatter_kernel(const int* __restrict__ src, const int* __restrict__ dst) {
    int gid  = blockIdx.x * blockDim.x + threadIdx.x;
    int edge = gid >> 5;
    int lane = gid & 31;
    if (edge >= N_EDGES) return;
    int   s = __ldg(src + edge);
    int   d = __ldg(dst + edge);
    float c = d_coef[edge];
    float4 zv = __ldg(reinterpret_cast<const float4*>(d_z + (size_t)s * DIM) + lane);
    float* addr = d_hnew + (size_t)d * DIM + 4 * lane;
    asm volatile("red.global.add.v4.f32 [%0], {%1, %2, %3, %4};"
                 :: "l"(addr), "f"(c * zv.x), "f"(c * zv.y), "f"(c * zv.z), "f"(c * zv.w)
                 : "memory");
}

// ---------------- BN column stats -------------------------------------------
__global__ void stats_kernel() {
    int col = threadIdx.x;              // 128 threads
    double s = 0.0, sq = 0.0;
    for (int row = blockIdx.x; row < N_NODES; row += gridDim.x) {
        float v = d_hnew[(size_t)row * DIM + col];
        s  += (double)v;
        sq += (double)v * (double)v;
    }
    atomicAdd(&d_colsum[col], s);
    atomicAdd(&d_colsq[col], sq);
}

__global__ void finalize_kernel(const float* __restrict__ gamma,
                                const float* __restrict__ beta) {
    int c = threadIdx.x;
    if (c >= DIM) return;
    double mu  = d_colsum[c] / (double)N_NODES;
    double var = d_colsq[c] / (double)N_NODES - mu * mu;
    float rstd = rsqrtf((float)var + EPS_BN);
    float g = __ldg(gamma + c);
    float b = __ldg(beta + c);
    d_scale[c] = rstd * g;
    d_shift[c] = b - (float)mu * rstd * g;
}

// ---------------- normalize + ELU -------------------------------------------
__global__ void output_kernel(float* __restrict__ out) {
    int i = blockIdx.x * blockDim.x + threadIdx.x;
    if (i >= N_NODES * DIM) return;
    int c = i & (DIM - 1);
    float x = d_hnew[i] * d_scale[c] + d_shift[c];
    out[i] = (x > 0.f) ? x : expm1f(x);
}

// ---------------- launch -----------------------------------------------------
extern "C" void kernel_launch(void* const* d_in, const int* in_sizes, int n_in,
                              void* d_out, int out_size) {
    const float* h      = (const float*)d_in[0];
    const int*   src    = (const int*)  d_in[1];
    const int*   dst    = (const int*)  d_in[2];
    const float* sigma  = (const float*)d_in[3];
    const float* fc_w   = (const float*)d_in[4];
    const float* fc_b   = (const float*)d_in[5];
    const float* attn_w = (const float*)d_in[6];
    const float* attn_b = (const float*)d_in[7];
    const float* gamma  = (const float*)d_in[8];
    const float* beta   = (const float*)d_in[9];
    float* out = (float*)d_out;

    init_kernel<<<4096, 256>>>();
    gemm_kernel<<<(N_NODES + 63) / 64, 256>>>(h, fc_w, fc_b, attn_w);

    const int EB = (N_EDGES + 255) / 256;
    edge1_kernel<<<EB, 256>>>(src, dst, attn_b);
    edge2_kernel<<<EB, 256>>>(dst, sigma);
    edge3_kernel<<<EB, 256>>>(dst, sigma);

    // one warp per edge: 8 edges per 256-thread block
    scatter_kernel<<<(N_EDGES + 7) / 8, 256>>>(src, dst);

    stats_kernel<<<512, 128>>>();
    finalize_kernel<<<1, 128>>>(gamma, beta);
    output_kernel<<<(N_NODES * DIM + 1023) / 1024, 1024>>>(out);
}